// round 15
// baseline (speedup 1.0000x reference)
#include <cuda_runtime.h>
#include <cuda_bf16.h>
#include <cstdint>

// Shapes (fixed per reference):
//   x      [16, 128, 128, 128] fp32
//   style  [16, 512]           fp32
//   weight [1, 128, 128, 3, 3] fp32  (co, ci, ky, kx)
//   mod_w  [128, 512]          fp32
//   mod_b  [128]               fp32
//   out    [16, 128, 128, 128] fp32

#define B_    16
#define CIN   128
#define COUT  128
#define HH    128
#define WW    128
#define SDIM  512
#define KK    3
#define RPC   9            // K*K
#define KC    8            // ci per chunk
#define NCHUNK (CIN / KC)  // 16
#define WROWS (KC * RPC)   // 72 rows of sW per chunk
#define XROWS (KC * 3)     // 24 rows of sX per chunk
#define XPITCH 132         // 130 needed (halo), padded to 132 (16B-aligned rows)

// Scratch (allocation-free rule: __device__ globals)
__device__ float g_s[B_ * CIN];        // modulation scalars s[b][ci]
__device__ float g_dec[B_ * COUT];     // demod coefficients
__device__ float g_wm[B_ * CIN * RPC * COUT]; // modulated weights [b][ci*9+r][co]

// ---------------------------------------------------------------------------
// Kernel A: s[b][ci] = mod_b[ci] + sum_k style[b][k] * mod_w[ci][k]
// ---------------------------------------------------------------------------
__global__ void mc_style_kernel(const float* __restrict__ style,
                                const float* __restrict__ mod_w,
                                const float* __restrict__ mod_b,
                                float* __restrict__ s_out)
{
    __shared__ float st[SDIM];
    int b  = blockIdx.x;
    int ci = threadIdx.x;           // 128 threads
    for (int k = threadIdx.x; k < SDIM; k += blockDim.x)
        st[k] = style[b * SDIM + k];
    __syncthreads();

    const float* mw = mod_w + ci * SDIM;
    float acc = mod_b[ci];
    #pragma unroll 4
    for (int k = 0; k < SDIM; ++k)
        acc += st[k] * mw[k];
    s_out[b * CIN + ci] = acc;
}

// ---------------------------------------------------------------------------
// Kernel B: dec[b][co] = rsqrt( sum_{ci,r} (weight[co,ci,r]*s[b,ci])^2 + eps )
// ---------------------------------------------------------------------------
__global__ void mc_decoef_kernel(const float* __restrict__ weight,
                                 const float* __restrict__ s,
                                 float* __restrict__ dec)
{
    int co = blockIdx.x;
    int b  = blockIdx.y;
    int ci = threadIdx.x;           // 128 threads

    float sv = s[b * CIN + ci];
    const float* wr = weight + (co * CIN + ci) * RPC;
    float q = 0.f;
    #pragma unroll
    for (int r = 0; r < RPC; ++r) {
        float w = wr[r];
        q += w * w;
    }
    q *= sv * sv;

    __shared__ float red[128];
    red[ci] = q;
    __syncthreads();
    #pragma unroll
    for (int off = 64; off > 0; off >>= 1) {
        if (ci < off) red[ci] += red[ci + off];
        __syncthreads();
    }
    if (ci == 0) dec[b * COUT + co] = rsqrtf(red[0] + 1e-8f);
}

// ---------------------------------------------------------------------------
// Kernel C: g_wm[((b*128+ci)*9+r)*128 + co] = weight[co,ci,r] * s[b,ci] * dec[b,co]
//   (coalesced writes; scattered weight reads served from L2 — weight is 576 KB)
// ---------------------------------------------------------------------------
__global__ void mc_wm_kernel(const float* __restrict__ weight,
                             const float* __restrict__ s,
                             const float* __restrict__ dec,
                             float* __restrict__ wm)
{
    int idx = blockIdx.x * blockDim.x + threadIdx.x;
    if (idx >= B_ * CIN * RPC * COUT) return;
    int co   = idx & (COUT - 1);
    int rest = idx >> 7;            // (b*128+ci)*9 + r
    int r    = rest % RPC;
    int q    = rest / RPC;          // b*128 + ci
    int ci   = q & (CIN - 1);
    int b    = q >> 7;
    wm[idx] = weight[(co * CIN + ci) * RPC + r] * s[b * CIN + ci] * dec[b * COUT + co];
}

// ---------------------------------------------------------------------------
// Conv kernel: one CTA per (b, y). Computes out[b, 0:128, y, 0:128].
// Implicit GEMM: M=co(128), N=x(128), K=ci*9(1152), chunked by 8 ci.
// 256 threads, each owns an 8x8 register tile with split fragments:
//   co_i : ty*4+{0..3}  and  64+ty*4+{0..3}
//   x_j  : tx*4+{0..3}  and  64+tx*4+{0..3}
// => all smem fragment loads are conflict-free LDS.128, stores are STG.128.
// ---------------------------------------------------------------------------
__global__ void __launch_bounds__(256, 2)
mc_conv_kernel(const float* __restrict__ x,
               const float* __restrict__ wm,
               float* __restrict__ out)
{
    extern __shared__ float smem[];
    float* sW = smem;                       // [WROWS][128]
    float* sX = smem + WROWS * COUT;        // [XROWS][XPITCH]

    const int y  = blockIdx.x;
    const int b  = blockIdx.y;
    const int t  = threadIdx.x;
    const int tx = t & 15;
    const int ty = t >> 4;

    // zero sX once (halo columns + out-of-range rows stay zero forever)
    for (int i = t; i < XROWS * XPITCH; i += 256) sX[i] = 0.f;

    float acc[8][8];
    #pragma unroll
    for (int i = 0; i < 8; ++i)
        #pragma unroll
        for (int j = 0; j < 8; ++j) acc[i][j] = 0.f;

    const float* xb  = x  + (size_t)b * CIN * HH * WW;
    const float* wmb = wm + (size_t)b * CIN * RPC * COUT;

    for (int c = 0; c < NCHUNK; ++c) {
        __syncthreads();

        // --- load weight tile: 72*128 floats = 2304 float4, 9 per thread ---
        {
            const float4* src = reinterpret_cast<const float4*>(wmb + c * WROWS * COUT);
            float4* dst = reinterpret_cast<float4*>(sW);
            #pragma unroll
            for (int i = 0; i < 9; ++i)
                dst[t + i * 256] = src[t + i * 256];
        }

        // --- load input rows: 24 rows x 32 float4, 3 per thread ---
        #pragma unroll
        for (int k = 0; k < 3; ++k) {
            int f    = t + k * 256;        // 0..767
            int row  = f >> 5;             // 0..23  (ci*3 + ky)
            int col4 = f & 31;             // float4 index in row
            int ci   = row / 3;
            int ky   = row - ci * 3;
            int yy   = y + ky - 1;
            if ((unsigned)yy < (unsigned)HH) {
                float4 v = *reinterpret_cast<const float4*>(
                    xb + ((size_t)(c * KC + ci) * HH + yy) * WW + col4 * 4);
                float* d = sX + row * XPITCH + 1 + col4 * 4;
                d[0] = v.x; d[1] = v.y; d[2] = v.z; d[3] = v.w;
            }
        }
        __syncthreads();

        // --- compute ---
        #pragma unroll 1
        for (int ci = 0; ci < KC; ++ci) {
            #pragma unroll
            for (int ky = 0; ky < 3; ++ky) {
                const float* xr = sX + (ci * 3 + ky) * XPITCH;
                // fragments: cols tx*4 .. tx*4+7 and 64+tx*4 .. 64+tx*4+7
                float xv0[8], xv1[8];
                {
                    float4 a = *reinterpret_cast<const float4*>(xr + tx * 4);
                    float4 b2 = *reinterpret_cast<const float4*>(xr + tx * 4 + 4);
                    xv0[0]=a.x; xv0[1]=a.y; xv0[2]=a.z; xv0[3]=a.w;
                    xv0[4]=b2.x; xv0[5]=b2.y; xv0[6]=b2.z; xv0[7]=b2.w;
                    float4 c1 = *reinterpret_cast<const float4*>(xr + 64 + tx * 4);
                    float4 d1 = *reinterpret_cast<const float4*>(xr + 64 + tx * 4 + 4);
                    xv1[0]=c1.x; xv1[1]=c1.y; xv1[2]=c1.z; xv1[3]=c1.w;
                    xv1[4]=d1.x; xv1[5]=d1.y; xv1[6]=d1.z; xv1[7]=d1.w;
                }
                #pragma unroll
                for (int kx = 0; kx < 3; ++kx) {
                    const float* wr = sW + (ci * RPC + ky * 3 + kx) * COUT;
                    float4 w0 = *reinterpret_cast<const float4*>(wr + ty * 4);
                    float4 w1 = *reinterpret_cast<const float4*>(wr + 64 + ty * 4);
                    float wv[8] = {w0.x, w0.y, w0.z, w0.w, w1.x, w1.y, w1.z, w1.w};
                    #pragma unroll
                    for (int i = 0; i < 8; ++i) {
                        #pragma unroll
                        for (int j = 0; j < 4; ++j) {
                            acc[i][j]     += wv[i] * xv0[j + kx];
                            acc[i][j + 4] += wv[i] * xv1[j + kx];
                        }
                    }
                }
            }
        }
    }

    // --- store: out[b][co][y][x] ---
    float* ob = out + ((size_t)b * COUT * HH + y) * WW;
    #pragma unroll
    for (int i = 0; i < 8; ++i) {
        int co = (i < 4) ? (ty * 4 + i) : (64 + ty * 4 + (i - 4));
        float* orow = ob + (size_t)co * HH * WW;
        *reinterpret_cast<float4*>(orow + tx * 4) =
            make_float4(acc[i][0], acc[i][1], acc[i][2], acc[i][3]);
        *reinterpret_cast<float4*>(orow + 64 + tx * 4) =
            make_float4(acc[i][4], acc[i][5], acc[i][6], acc[i][7]);
    }
}

// ---------------------------------------------------------------------------
extern "C" void kernel_launch(void* const* d_in, const int* in_sizes, int n_in,
                              void* d_out, int out_size)
{
    const float* x      = (const float*)d_in[0];
    const float* style  = (const float*)d_in[1];
    const float* weight = (const float*)d_in[2];
    const float* mod_w  = (const float*)d_in[3];
    const float* mod_b  = (const float*)d_in[4];
    float* out = (float*)d_out;

    float *s_ptr, *dec_ptr, *wm_ptr;
    cudaGetSymbolAddress((void**)&s_ptr,   g_s);
    cudaGetSymbolAddress((void**)&dec_ptr, g_dec);
    cudaGetSymbolAddress((void**)&wm_ptr,  g_wm);

    const int smem_bytes = (WROWS * COUT + XROWS * XPITCH) * (int)sizeof(float); // 49536
    cudaFuncSetAttribute(mc_conv_kernel,
                         cudaFuncAttributeMaxDynamicSharedMemorySize, smem_bytes);

    mc_style_kernel<<<B_, 128>>>(style, mod_w, mod_b, s_ptr);
    mc_decoef_kernel<<<dim3(COUT, B_), 128>>>(weight, s_ptr, dec_ptr);
    {
        int total = B_ * CIN * RPC * COUT;
        mc_wm_kernel<<<(total + 255) / 256, 256>>>(weight, s_ptr, dec_ptr, wm_ptr);
    }
    mc_conv_kernel<<<dim3(HH, B_), 256, smem_bytes>>>(x, wm_ptr, out);
}